// round 4
// baseline (speedup 1.0000x reference)
#include <cuda_runtime.h>
#include <cstdint>
#include <math.h>

// ---------------------------------------------------------------------------
// LSTM  B=64 S=512 D=1024 H=1024 F=1024
//  1) G_pre = Xt @ WxT^T + b_g      (tf32 GEMM, M=32768 N=4096 K=1024)
//  2) 512 x step kernel: gates = G_pre[t] + h@WhT^T ; fused LSTM elementwise
//  3) out = Hall @ WoT^T + b_out    (tf32 GEMM, M=32768 N=1024 K=1024)
// Gate columns interleaved: n = 4*unit + gate.
// ---------------------------------------------------------------------------

#define DEVINL __device__ __forceinline__

// ---------------- static device scratch (no runtime allocation) ------------
__device__ float g_Xt  [(size_t)32768 * 1024];   // x as (t,b) rows, tf32-rounded
__device__ float g_Gpre[(size_t)32768 * 4096];   // x-part of gates (+bias)
__device__ float g_Hall[(size_t)32768 * 1024];   // all h_t, tf32-rounded
__device__ float g_WxT [(size_t)4096 * 1024];    // [n][k] interleaved, x rows
__device__ float g_WhT [(size_t)4096 * 1024];    // [n][k] interleaved, h rows
__device__ float g_WoT [(size_t)1024 * 1024];    // W_out^T [f][h]
__device__ float g_bg  [4096];                   // gate bias, interleaved
__device__ float g_h   [2][64 * 1024];           // ping-pong recurrent state
__device__ float g_c   [64 * 1024];              // cell state

// ---------------- helpers ---------------------------------------------------
DEVINL uint32_t f2tf32(float x) {
    uint32_t r; asm("cvt.rna.tf32.f32 %0, %1;" : "=r"(r) : "f"(x)); return r;
}
DEVINL float tf32r(float x) { return __uint_as_float(f2tf32(x)); }

DEVINL void cpa16(void* dst, const void* src) {
    uint32_t d = (uint32_t)__cvta_generic_to_shared(dst);
    asm volatile("cp.async.cg.shared.global [%0], [%1], 16;\n" :: "r"(d), "l"(src));
}
DEVINL void cp_commit() { asm volatile("cp.async.commit_group;\n"); }
template <int N> DEVINL void cp_wait() { asm volatile("cp.async.wait_group %0;\n" :: "n"(N)); }

DEVINL void mma_tf32(float* c, const uint32_t* a, const uint32_t* b) {
    asm volatile(
        "mma.sync.aligned.m16n8k8.row.col.f32.tf32.tf32.f32 "
        "{%0,%1,%2,%3},{%4,%5,%6,%7},{%8,%9},{%0,%1,%2,%3};\n"
        : "+f"(c[0]), "+f"(c[1]), "+f"(c[2]), "+f"(c[3])
        : "r"(a[0]), "r"(a[1]), "r"(a[2]), "r"(a[3]), "r"(b[0]), "r"(b[1]));
}
DEVINL float sigm(float x) { return 1.f / (1.f + __expf(-x)); }

// ---------------- prep kernels ---------------------------------------------
// x[b,t,d] -> g_Xt[(t*64+b)*1024 + d] (tf32-rounded). grid 32768 x 256
__global__ void __launch_bounds__(256) k_prep_x(const float* __restrict__ x) {
    size_t p = (size_t)blockIdx.x * 256 + threadIdx.x;
    int d4 = (int)(p & 255);
    size_t m = p >> 8;
    int b = (int)(m & 63), t = (int)(m >> 6);
    float4 v = *(const float4*)(x + ((size_t)b * 512 + t) * 1024 + (size_t)d4 * 4);
    v.x = tf32r(v.x); v.y = tf32r(v.y); v.z = tf32r(v.z); v.w = tf32r(v.w);
    *(float4*)(g_Xt + m * 1024 + (size_t)d4 * 4) = v;
}

// gate weights [2048,1024] -> WxT / WhT with gate interleave. grid 8192, (32,8)
__global__ void k_prep_w(const float* __restrict__ Wf, const float* __restrict__ Wi,
                         const float* __restrict__ Wc, const float* __restrict__ Wo) {
    __shared__ float tile[32][33];
    int bid = blockIdx.x;
    int s    = bid >> 12;         // 0 = x rows, 1 = h rows
    int gate = (bid >> 10) & 3;
    int kt   = (bid >> 5) & 31;
    int ut   = bid & 31;
    const float* W = (gate == 0) ? Wf : (gate == 1) ? Wi : (gate == 2) ? Wc : Wo;
    int tx = threadIdx.x, ty = threadIdx.y;
#pragma unroll
    for (int r = 0; r < 4; r++) {
        int k = kt * 32 + ty + r * 8;
        tile[ty + r * 8][tx] = W[(size_t)(s * 1024 + k) * 1024 + ut * 32 + tx];
    }
    __syncthreads();
    float* WT = s ? g_WhT : g_WxT;
#pragma unroll
    for (int r = 0; r < 4; r++) {
        int ul = ty + r * 8;
        int n = 4 * (ut * 32 + ul) + gate;
        WT[(size_t)n * 1024 + kt * 32 + tx] = tf32r(tile[tx][ul]);
    }
}

// W_out [1024][1024] -> g_WoT[f][h]. grid 1024, (32,8)
__global__ void k_prep_wout(const float* __restrict__ Wout) {
    __shared__ float tile[32][33];
    int ft = blockIdx.x & 31, ht = blockIdx.x >> 5;
    int tx = threadIdx.x, ty = threadIdx.y;
#pragma unroll
    for (int r = 0; r < 4; r++) {
        int h = ht * 32 + ty + r * 8;
        tile[ty + r * 8][tx] = Wout[(size_t)h * 1024 + ft * 32 + tx];
    }
    __syncthreads();
#pragma unroll
    for (int r = 0; r < 4; r++) {
        int fl = ty + r * 8;
        int f = ft * 32 + fl;
        g_WoT[(size_t)f * 1024 + ht * 32 + tx] = tf32r(tile[tx][fl]);
    }
}

// interleaved bias + state init. grid 256 x 256
__global__ void __launch_bounds__(256) k_prep_misc(
        const float* __restrict__ bf, const float* __restrict__ bi,
        const float* __restrict__ bc, const float* __restrict__ bo,
        const float* __restrict__ h0, const float* __restrict__ c0) {
    int i = blockIdx.x * 256 + threadIdx.x;      // 0..65535
    if (i < 4096) {
        int u = i >> 2, gt = i & 3;
        const float* b = (gt == 0) ? bf : (gt == 1) ? bi : (gt == 2) ? bc : bo;
        g_bg[i] = b[u];
    }
    g_h[0][i] = tf32r(h0[i]);
    g_c[i]    = c0[i];
}

// ---------------- big tf32 GEMM: BM=128 BN=64 BK=32, 256 thr, 3-stage ------
// mode 0: g_Gpre = g_Xt @ g_WxT^T + g_bg   (N=4096)
// mode 1: out    = g_Hall @ g_WoT^T + b_out, row m=(t*64+b) -> out[(b*512+t)*1024]
__global__ void __launch_bounds__(256) k_gemm(float* __restrict__ Cpost,
                                              const float* __restrict__ bias_post,
                                              int mode) {
    extern __shared__ float sm[];
    const float* A  = mode ? g_Hall : g_Xt;
    const float* BT = mode ? g_WoT  : g_WxT;
    float* As = sm;                    // [3][128][36]
    float* Bs = sm + 3 * 128 * 36;     // [3][64][36]

    const int tid = threadIdx.x, lane = tid & 31, wid = tid >> 5;
    const int wm = wid & 3, wn = wid >> 2;
    const int g = lane >> 2, tg = lane & 3;
    const int m0 = blockIdx.y * 128;
    const int n0 = blockIdx.x * 64;

    float acc[2][4][4];
#pragma unroll
    for (int i = 0; i < 2; i++)
#pragma unroll
        for (int j = 0; j < 4; j++)
#pragma unroll
            for (int k = 0; k < 4; k++) acc[i][j][k] = 0.f;

    auto issue = [&](int stg, int kb) {
        float* as = As + stg * 128 * 36;
        float* bs = Bs + stg * 64 * 36;
#pragma unroll
        for (int r = 0; r < 4; r++) {
            int f = tid + r * 256; int row = f >> 3, c4 = f & 7;
            cpa16(&as[row * 36 + c4 * 4],
                  A + (size_t)(m0 + row) * 1024 + kb + c4 * 4);
        }
#pragma unroll
        for (int r = 0; r < 2; r++) {
            int f = tid + r * 256; int row = f >> 3, c4 = f & 7;
            cpa16(&bs[row * 36 + c4 * 4],
                  BT + (size_t)(n0 + row) * 1024 + kb + c4 * 4);
        }
    };

    issue(0, 0);  cp_commit();
    issue(1, 32); cp_commit();

    for (int kbi = 0; kbi < 32; kbi++) {
        cp_wait<1>();
        __syncthreads();
        const uint32_t* as = (const uint32_t*)(As + (kbi % 3) * 128 * 36);
        const uint32_t* bs = (const uint32_t*)(Bs + (kbi % 3) * 64 * 36);
#pragma unroll
        for (int kk = 0; kk < 32; kk += 8) {
            uint32_t a[2][4], b[4][2];
#pragma unroll
            for (int mt = 0; mt < 2; mt++) {
                int r0 = wm * 32 + mt * 16 + g;
                a[mt][0] = as[r0 * 36 + kk + tg];
                a[mt][1] = as[(r0 + 8) * 36 + kk + tg];
                a[mt][2] = as[r0 * 36 + kk + 4 + tg];
                a[mt][3] = as[(r0 + 8) * 36 + kk + 4 + tg];
            }
#pragma unroll
            for (int nt = 0; nt < 4; nt++) {
                int nr = wn * 32 + nt * 8 + g;
                b[nt][0] = bs[nr * 36 + kk + tg];
                b[nt][1] = bs[nr * 36 + kk + 4 + tg];
            }
#pragma unroll
            for (int mt = 0; mt < 2; mt++)
#pragma unroll
                for (int nt = 0; nt < 4; nt++) mma_tf32(acc[mt][nt], a[mt], b[nt]);
        }
        if (kbi + 2 < 32) issue((kbi + 2) % 3, (kbi + 2) * 32);
        cp_commit();
    }

    // epilogue
#pragma unroll
    for (int mt = 0; mt < 2; mt++) {
#pragma unroll
        for (int nt = 0; nt < 4; nt++) {
            int row = m0 + wm * 32 + mt * 16 + g;
            int col = n0 + wn * 32 + nt * 8 + 2 * tg;
#pragma unroll
            for (int h = 0; h < 2; h++) {
                int gr = row + h * 8;
                float b0, b1;
                float v0 = acc[mt][nt][h * 2 + 0];
                float v1 = acc[mt][nt][h * 2 + 1];
                if (mode == 0) { b0 = g_bg[col]; b1 = g_bg[col + 1]; }
                else           { b0 = bias_post[col]; b1 = bias_post[col + 1]; }
                float2 v = make_float2(v0 + b0, v1 + b1);
                if (mode == 0) {
                    *(float2*)(g_Gpre + (size_t)gr * 4096 + col) = v;
                } else {
                    size_t o = ((size_t)(gr & 63) * 512 + (gr >> 6)) * 1024 + col;
                    *(float2*)(Cpost + o) = v;
                }
            }
        }
    }
}

// ---------------- recurrent step: M=64 N=4096(BN=32) K=1024 ----------------
// grid 128 CTAs x 256 thr. CTA owns units [n0/4, n0/4+8) -> full gate quads.
__global__ void __launch_bounds__(256) k_step(int t) {
    __shared__ __align__(16) float sm[3 * 96 * 36];   // stage: A 64x36, B 32x36
    const float* hin  = g_h[t & 1];
    float* hout       = g_h[(t + 1) & 1];
    float* hall       = g_Hall + (size_t)t * 64 * 1024;
    const float* gpre = g_Gpre + (size_t)t * 64 * 4096;

    const int tid = threadIdx.x, lane = tid & 31, wid = tid >> 5;
    const int wm = wid & 3, wn = wid >> 2;
    const int g = lane >> 2, tg = lane & 3;
    const int n0 = blockIdx.x * 32;

    float acc[2][4];
#pragma unroll
    for (int i = 0; i < 2; i++)
#pragma unroll
        for (int k = 0; k < 4; k++) acc[i][k] = 0.f;

    auto issue = [&](int stg, int kb) {
        float* as = sm + stg * 3456;
        float* bs = as + 64 * 36;
#pragma unroll
        for (int r = 0; r < 2; r++) {
            int f = tid + r * 256; int row = f >> 3, c4 = f & 7;
            cpa16(&as[row * 36 + c4 * 4], hin + (size_t)row * 1024 + kb + c4 * 4);
        }
        {
            int row = tid >> 3, c4 = tid & 7;
            cpa16(&bs[row * 36 + c4 * 4],
                  g_WhT + (size_t)(n0 + row) * 1024 + kb + c4 * 4);
        }
    };

    issue(0, 0);  cp_commit();
    issue(1, 32); cp_commit();

    for (int kbi = 0; kbi < 32; kbi++) {
        cp_wait<1>();
        __syncthreads();
        const uint32_t* as = (const uint32_t*)(sm + (kbi % 3) * 3456);
        const uint32_t* bs = as + 64 * 36;
#pragma unroll
        for (int kk = 0; kk < 32; kk += 8) {
            uint32_t a[4], b[2][2];
            int r0 = wm * 16 + g;
            a[0] = as[r0 * 36 + kk + tg];
            a[1] = as[(r0 + 8) * 36 + kk + tg];
            a[2] = as[r0 * 36 + kk + 4 + tg];
            a[3] = as[(r0 + 8) * 36 + kk + 4 + tg];
#pragma unroll
            for (int nt = 0; nt < 2; nt++) {
                int nr = wn * 16 + nt * 8 + g;
                b[nt][0] = bs[nr * 36 + kk + tg];
                b[nt][1] = bs[nr * 36 + kk + 4 + tg];
            }
            mma_tf32(acc[0], a, b[0]);
            mma_tf32(acc[1], a, b[1]);
        }
        if (kbi + 2 < 32) issue((kbi + 2) % 3, (kbi + 2) * 32);
        cp_commit();
    }

    // gate exchange through smem (reuse stage memory)
    __syncthreads();
    float* gb = sm;   // [64][36], cols 0..31 used
#pragma unroll
    for (int nt = 0; nt < 2; nt++) {
        int row = wm * 16 + g, col = wn * 16 + nt * 8 + 2 * tg;
        gb[row * 36 + col]           = acc[nt][0];
        gb[row * 36 + col + 1]       = acc[nt][1];
        gb[(row + 8) * 36 + col]     = acc[nt][2];
        gb[(row + 8) * 36 + col + 1] = acc[nt][3];
    }
    __syncthreads();

    // fused LSTM elementwise: 64 b x 8 units per CTA
#pragma unroll
    for (int r = 0; r < 2; r++) {
        int item = tid + r * 256;        // 0..511
        int b = item >> 3, uu = item & 7;
        int cl = 4 * uu;
        const float* gp = gpre + (size_t)b * 4096 + n0 + cl;
        float gf = gb[b * 36 + cl]     + gp[0];
        float gi = gb[b * 36 + cl + 1] + gp[1];
        float gc = gb[b * 36 + cl + 2] + gp[2];
        float go = gb[b * 36 + cl + 3] + gp[3];
        float f  = sigm(gf);
        float i  = sigm(gi);
        float ch = tanhf(gc);
        float o  = sigm(go);
        int U = (n0 >> 2) + uu;
        size_t ci = (size_t)b * 1024 + U;
        float cn = f * g_c[ci] + i * ch;
        g_c[ci] = cn;
        float hr = tf32r(o * tanhf(cn));
        hout[ci] = hr;
        hall[ci] = hr;
    }
}

// ---------------- launch -----------------------------------------------------
extern "C" void kernel_launch(void* const* d_in, const int* in_sizes, int n_in,
                              void* d_out, int out_size) {
    const float* x    = (const float*)d_in[0];
    const float* h0   = (const float*)d_in[1];
    const float* c0   = (const float*)d_in[2];
    const float* W_f  = (const float*)d_in[3];
    const float* b_f  = (const float*)d_in[4];
    const float* W_i  = (const float*)d_in[5];
    const float* b_i  = (const float*)d_in[6];
    const float* W_c  = (const float*)d_in[7];
    const float* b_c  = (const float*)d_in[8];
    const float* W_o  = (const float*)d_in[9];
    const float* b_o  = (const float*)d_in[10];
    const float* W_out = (const float*)d_in[11];
    const float* b_out = (const float*)d_in[12];
    float* out = (float*)d_out;

    cudaFuncSetAttribute(k_gemm, cudaFuncAttributeMaxDynamicSharedMemorySize, 82944);

    k_prep_x<<<32768, 256>>>(x);
    k_prep_w<<<8192, dim3(32, 8)>>>(W_f, W_i, W_c, W_o);
    k_prep_wout<<<1024, dim3(32, 8)>>>(W_out);
    k_prep_misc<<<256, 256>>>(b_f, b_i, b_c, b_o, h0, c0);

    // pre-GEMM: G_pre (M=32768, N=4096)
    k_gemm<<<dim3(64, 256), 256, 82944>>>(nullptr, nullptr, 0);

    // 512 sequential steps
    for (int t = 0; t < 512; t++) k_step<<<128, 256>>>(t);

    // post-GEMM: out (M=32768, N=1024)
    k_gemm<<<dim3(16, 256), 256, 82944>>>(out, b_out, 1);
}

// round 5
// speedup vs baseline: 1.0305x; 1.0305x over previous
#include <cuda_runtime.h>
#include <cstdint>
#include <math.h>

// ---------------------------------------------------------------------------
// LSTM  B=64 S=512 D=1024 H=1024 F=1024
//  1) G_pre = Xt @ WxT^T + b_g      (tf32 GEMM, M=32768 N=4096 K=1024)
//  2) ONE persistent kernel, 128 CTAs, 512 steps:
//       gates = G_pre[t] + h@WhT^T ; fused LSTM elementwise
//     W_h slice lives in SMEM for the whole kernel; c lives in registers;
//     steps separated by a flag/sense software grid barrier.
//  3) out = Hall @ WoT^T + b_out    (tf32 GEMM, M=32768 N=1024 K=1024)
// Gate columns interleaved: n = 4*unit + gate.
// ---------------------------------------------------------------------------

#define DEVINL __device__ __forceinline__

// ---------------- static device scratch (no runtime allocation) ------------
__device__ float g_Xt  [(size_t)32768 * 1024];   // x as (t,b) rows, tf32-rounded
__device__ float g_Gpre[(size_t)32768 * 4096];   // x-part of gates (+bias)
__device__ float g_Hall[(size_t)32768 * 1024];   // all h_t, tf32-rounded
__device__ float g_WxT [(size_t)4096 * 1024];    // [n][k] interleaved, x rows
__device__ float g_WhT [(size_t)4096 * 1024];    // [n][k] interleaved, h rows
__device__ float g_WoT [(size_t)1024 * 1024];    // W_out^T [f][h]
__device__ float g_bg  [4096];                   // gate bias, interleaved
__device__ float g_h   [2][64 * 1024];           // ping-pong recurrent state
__device__ float g_c   [64 * 1024];              // cell state (init only)

// grid-barrier state: monotonic counters (never reset; base read per launch)
__device__ unsigned g_flags[128 * 32];           // flag i at [i*32] (own 128B line)
__device__ unsigned g_sense;

// ---------------- helpers ---------------------------------------------------
DEVINL uint32_t f2tf32(float x) {
    uint32_t r; asm("cvt.rna.tf32.f32 %0, %1;" : "=r"(r) : "f"(x)); return r;
}
DEVINL float tf32r(float x) { return __uint_as_float(f2tf32(x)); }

DEVINL void cpa16(void* dst, const void* src) {
    uint32_t d = (uint32_t)__cvta_generic_to_shared(dst);
    asm volatile("cp.async.cg.shared.global [%0], [%1], 16;\n" :: "r"(d), "l"(src));
}
DEVINL void cp_commit() { asm volatile("cp.async.commit_group;\n"); }
template <int N> DEVINL void cp_wait() { asm volatile("cp.async.wait_group %0;\n" :: "n"(N)); }

DEVINL void mma_tf32(float* c, const uint32_t* a, const uint32_t* b) {
    asm volatile(
        "mma.sync.aligned.m16n8k8.row.col.f32.tf32.tf32.f32 "
        "{%0,%1,%2,%3},{%4,%5,%6,%7},{%8,%9},{%0,%1,%2,%3};\n"
        : "+f"(c[0]), "+f"(c[1]), "+f"(c[2]), "+f"(c[3])
        : "r"(a[0]), "r"(a[1]), "r"(a[2]), "r"(a[3]), "r"(b[0]), "r"(b[1]));
}
DEVINL float sigm(float x) { return 1.f / (1.f + __expf(-x)); }

DEVINL unsigned ldacq(const unsigned* p) {
    unsigned v; asm volatile("ld.acquire.gpu.global.u32 %0, [%1];" : "=r"(v) : "l"(p)); return v;
}
DEVINL void strel(unsigned* p, unsigned v) {
    asm volatile("st.release.gpu.global.u32 [%0], %1;" :: "l"(p), "r"(v));
}

// ---------------- prep kernels ---------------------------------------------
// x[b,t,d] -> g_Xt[(t*64+b)*1024 + d] (tf32-rounded). grid 32768 x 256
__global__ void __launch_bounds__(256) k_prep_x(const float* __restrict__ x) {
    size_t p = (size_t)blockIdx.x * 256 + threadIdx.x;
    int d4 = (int)(p & 255);
    size_t m = p >> 8;
    int b = (int)(m & 63), t = (int)(m >> 6);
    float4 v = *(const float4*)(x + ((size_t)b * 512 + t) * 1024 + (size_t)d4 * 4);
    v.x = tf32r(v.x); v.y = tf32r(v.y); v.z = tf32r(v.z); v.w = tf32r(v.w);
    *(float4*)(g_Xt + m * 1024 + (size_t)d4 * 4) = v;
}

// gate weights [2048,1024] -> WxT / WhT with gate interleave. grid 8192, (32,8)
__global__ void k_prep_w(const float* __restrict__ Wf, const float* __restrict__ Wi,
                         const float* __restrict__ Wc, const float* __restrict__ Wo) {
    __shared__ float tile[32][33];
    int bid = blockIdx.x;
    int s    = bid >> 12;         // 0 = x rows, 1 = h rows
    int gate = (bid >> 10) & 3;
    int kt   = (bid >> 5) & 31;
    int ut   = bid & 31;
    const float* W = (gate == 0) ? Wf : (gate == 1) ? Wi : (gate == 2) ? Wc : Wo;
    int tx = threadIdx.x, ty = threadIdx.y;
#pragma unroll
    for (int r = 0; r < 4; r++) {
        int k = kt * 32 + ty + r * 8;
        tile[ty + r * 8][tx] = W[(size_t)(s * 1024 + k) * 1024 + ut * 32 + tx];
    }
    __syncthreads();
    float* WT = s ? g_WhT : g_WxT;
#pragma unroll
    for (int r = 0; r < 4; r++) {
        int ul = ty + r * 8;
        int n = 4 * (ut * 32 + ul) + gate;
        WT[(size_t)n * 1024 + kt * 32 + tx] = tf32r(tile[tx][ul]);
    }
}

// W_out [1024][1024] -> g_WoT[f][h]. grid 1024, (32,8)
__global__ void k_prep_wout(const float* __restrict__ Wout) {
    __shared__ float tile[32][33];
    int ft = blockIdx.x & 31, ht = blockIdx.x >> 5;
    int tx = threadIdx.x, ty = threadIdx.y;
#pragma unroll
    for (int r = 0; r < 4; r++) {
        int h = ht * 32 + ty + r * 8;
        tile[ty + r * 8][tx] = Wout[(size_t)h * 1024 + ft * 32 + tx];
    }
    __syncthreads();
#pragma unroll
    for (int r = 0; r < 4; r++) {
        int fl = ty + r * 8;
        int f = ft * 32 + fl;
        g_WoT[(size_t)f * 1024 + ht * 32 + tx] = tf32r(tile[tx][fl]);
    }
}

// interleaved bias + state init. grid 256 x 256
__global__ void __launch_bounds__(256) k_prep_misc(
        const float* __restrict__ bf, const float* __restrict__ bi,
        const float* __restrict__ bc, const float* __restrict__ bo,
        const float* __restrict__ h0, const float* __restrict__ c0) {
    int i = blockIdx.x * 256 + threadIdx.x;      // 0..65535
    if (i < 4096) {
        int u = i >> 2, gt = i & 3;
        const float* b = (gt == 0) ? bf : (gt == 1) ? bi : (gt == 2) ? bc : bo;
        g_bg[i] = b[u];
    }
    g_h[0][i] = tf32r(h0[i]);
    g_c[i]    = c0[i];
}

// ---------------- big tf32 GEMM: BM=128 BN=64 BK=32, 256 thr, 3-stage ------
// mode 0: g_Gpre = g_Xt @ g_WxT^T + g_bg   (N=4096)
// mode 1: out    = g_Hall @ g_WoT^T + b_out, row m=(t*64+b) -> out[(b*512+t)*1024]
__global__ void __launch_bounds__(256) k_gemm(float* __restrict__ Cpost,
                                              const float* __restrict__ bias_post,
                                              int mode) {
    extern __shared__ float sm[];
    const float* A  = mode ? g_Hall : g_Xt;
    const float* BT = mode ? g_WoT  : g_WxT;
    float* As = sm;                    // [3][128][36]
    float* Bs = sm + 3 * 128 * 36;     // [3][64][36]

    const int tid = threadIdx.x, lane = tid & 31, wid = tid >> 5;
    const int wm = wid & 3, wn = wid >> 2;
    const int g = lane >> 2, tg = lane & 3;
    const int m0 = blockIdx.y * 128;
    const int n0 = blockIdx.x * 64;

    float acc[2][4][4];
#pragma unroll
    for (int i = 0; i < 2; i++)
#pragma unroll
        for (int j = 0; j < 4; j++)
#pragma unroll
            for (int k = 0; k < 4; k++) acc[i][j][k] = 0.f;

    auto issue = [&](int stg, int kb) {
        float* as = As + stg * 128 * 36;
        float* bs = Bs + stg * 64 * 36;
#pragma unroll
        for (int r = 0; r < 4; r++) {
            int f = tid + r * 256; int row = f >> 3, c4 = f & 7;
            cpa16(&as[row * 36 + c4 * 4],
                  A + (size_t)(m0 + row) * 1024 + kb + c4 * 4);
        }
#pragma unroll
        for (int r = 0; r < 2; r++) {
            int f = tid + r * 256; int row = f >> 3, c4 = f & 7;
            cpa16(&bs[row * 36 + c4 * 4],
                  BT + (size_t)(n0 + row) * 1024 + kb + c4 * 4);
        }
    };

    issue(0, 0);  cp_commit();
    issue(1, 32); cp_commit();

    for (int kbi = 0; kbi < 32; kbi++) {
        cp_wait<1>();
        __syncthreads();
        const uint32_t* as = (const uint32_t*)(As + (kbi % 3) * 128 * 36);
        const uint32_t* bs = (const uint32_t*)(Bs + (kbi % 3) * 64 * 36);
#pragma unroll
        for (int kk = 0; kk < 32; kk += 8) {
            uint32_t a[2][4], b[4][2];
#pragma unroll
            for (int mt = 0; mt < 2; mt++) {
                int r0 = wm * 32 + mt * 16 + g;
                a[mt][0] = as[r0 * 36 + kk + tg];
                a[mt][1] = as[(r0 + 8) * 36 + kk + tg];
                a[mt][2] = as[r0 * 36 + kk + 4 + tg];
                a[mt][3] = as[(r0 + 8) * 36 + kk + 4 + tg];
            }
#pragma unroll
            for (int nt = 0; nt < 4; nt++) {
                int nr = wn * 32 + nt * 8 + g;
                b[nt][0] = bs[nr * 36 + kk + tg];
                b[nt][1] = bs[nr * 36 + kk + 4 + tg];
            }
#pragma unroll
            for (int mt = 0; mt < 2; mt++)
#pragma unroll
                for (int nt = 0; nt < 4; nt++) mma_tf32(acc[mt][nt], a[mt], b[nt]);
        }
        if (kbi + 2 < 32) issue((kbi + 2) % 3, (kbi + 2) * 32);
        cp_commit();
    }

    // epilogue
#pragma unroll
    for (int mt = 0; mt < 2; mt++) {
#pragma unroll
        for (int nt = 0; nt < 4; nt++) {
            int row = m0 + wm * 32 + mt * 16 + g;
            int col = n0 + wn * 32 + nt * 8 + 2 * tg;
#pragma unroll
            for (int h = 0; h < 2; h++) {
                int gr = row + h * 8;
                float b0, b1;
                float v0 = acc[mt][nt][h * 2 + 0];
                float v1 = acc[mt][nt][h * 2 + 1];
                if (mode == 0) { b0 = g_bg[col]; b1 = g_bg[col + 1]; }
                else           { b0 = bias_post[col]; b1 = bias_post[col + 1]; }
                float2 v = make_float2(v0 + b0, v1 + b1);
                if (mode == 0) {
                    *(float2*)(g_Gpre + (size_t)gr * 4096 + col) = v;
                } else {
                    size_t o = ((size_t)(gr & 63) * 512 + (gr >> 6)) * 1024 + col;
                    *(float2*)(Cpost + o) = v;
                }
            }
        }
    }
}

// ---------------- persistent recurrence: 128 CTAs x 256 thr, 512 steps -----
// CTA owns gate columns [n0, n0+32) = units [n0/4, n0/4+8). W_h slice in SMEM.
static const int WSTRIDE = 1028;                      // bank-conflict-free
static const int REC_SMEM = (32 * WSTRIDE + 3 * 64 * 36) * 4;   // 159232 B

__global__ void __launch_bounds__(256) k_rec() {
    extern __shared__ float smr[];
    float* Wsh = smr;                     // [32][1028]
    float* Ast = smr + 32 * WSTRIDE;      // 3 stages of [64][36]; aliased as gb

    const int tid = threadIdx.x, lane = tid & 31, wid = tid >> 5;
    const int wm = wid & 3, wn = wid >> 2;
    const int g = lane >> 2, tg = lane & 3;
    const int n0 = blockIdx.x * 32;
    const int bid = blockIdx.x;

    // ---- load W_h slice into SMEM (stays for all 512 steps) ----
#pragma unroll 4
    for (int j = 0; j < 32; j++) {
        int f = tid + j * 256;            // float4 index, 8192 total
        int row = f >> 8, c4 = f & 255;
        float4 v = *(const float4*)(g_WhT + (size_t)(n0 + row) * 1024 + (size_t)c4 * 4);
        *(float4*)(Wsh + row * WSTRIDE + c4 * 4) = v;
    }

    // ---- cell state in registers for the whole kernel ----
    float creg[2];
#pragma unroll
    for (int r = 0; r < 2; r++) {
        int item = tid + r * 256;
        int b = item >> 3, uu = item & 7;
        creg[r] = g_c[(size_t)b * 1024 + (n0 >> 2) + uu];
    }

    // ---- barrier bases (monotonic counters; all equal at launch start) ----
    __shared__ unsigned sh_base;
    if (tid == 0) sh_base = ldacq(&g_sense);
    __syncthreads();
    const unsigned base = sh_base;

    const uint32_t* wu = (const uint32_t*)Wsh;

    for (int t = 0; t < 512; t++) {
        const float* hin  = g_h[t & 1];
        float* hout       = g_h[(t + 1) & 1];
        float* hall       = g_Hall + (size_t)t * 64 * 1024;
        const float* gpre = g_Gpre + (size_t)t * 64 * 4096;

        auto issueA = [&](int stg, int kb) {
            float* as = Ast + stg * 2304;
#pragma unroll
            for (int r = 0; r < 2; r++) {
                int f = tid + r * 256; int row = f >> 3, c4 = f & 7;
                cpa16(&as[row * 36 + c4 * 4], hin + (size_t)row * 1024 + kb + c4 * 4);
            }
        };

        float acc[2][4];
#pragma unroll
        for (int i = 0; i < 2; i++)
#pragma unroll
            for (int k = 0; k < 4; k++) acc[i][k] = 0.f;

        issueA(0, 0);  cp_commit();
        issueA(1, 32); cp_commit();

        for (int kbi = 0; kbi < 32; kbi++) {
            cp_wait<1>();
            __syncthreads();
            const uint32_t* as = (const uint32_t*)(Ast + (kbi % 3) * 2304);
            const int kc = kbi * 32;
#pragma unroll
            for (int kk = 0; kk < 32; kk += 8) {
                uint32_t a[4], b[2][2];
                int r0 = wm * 16 + g;
                a[0] = as[r0 * 36 + kk + tg];
                a[1] = as[(r0 + 8) * 36 + kk + tg];
                a[2] = as[r0 * 36 + kk + 4 + tg];
                a[3] = as[(r0 + 8) * 36 + kk + 4 + tg];
#pragma unroll
                for (int nt = 0; nt < 2; nt++) {
                    int nr = wn * 16 + nt * 8 + g;
                    b[nt][0] = wu[nr * WSTRIDE + kc + kk + tg];
                    b[nt][1] = wu[nr * WSTRIDE + kc + kk + 4 + tg];
                }
                mma_tf32(acc[0], a, b[0]);
                mma_tf32(acc[1], a, b[1]);
            }
            if (kbi + 2 < 32) issueA((kbi + 2) % 3, (kbi + 2) * 32);
            cp_commit();
        }

        // ---- gate exchange through smem (alias stage memory) ----
        __syncthreads();
        float* gb = Ast;                  // [64][36], cols 0..31 used
#pragma unroll
        for (int nt = 0; nt < 2; nt++) {
            int row = wm * 16 + g, col = wn * 16 + nt * 8 + 2 * tg;
            gb[row * 36 + col]           = acc[nt][0];
            gb[row * 36 + col + 1]       = acc[nt][1];
            gb[(row + 8) * 36 + col]     = acc[nt][2];
            gb[(row + 8) * 36 + col + 1] = acc[nt][3];
        }
        __syncthreads();

        // ---- fused LSTM elementwise: 64 b x 8 units per CTA ----
#pragma unroll
        for (int r = 0; r < 2; r++) {
            int item = tid + r * 256;
            int b = item >> 3, uu = item & 7;
            int cl = 4 * uu;
            float4 gp = *(const float4*)(gpre + (size_t)b * 4096 + n0 + cl);
            float gf = gb[b * 36 + cl]     + gp.x;
            float gi = gb[b * 36 + cl + 1] + gp.y;
            float gc = gb[b * 36 + cl + 2] + gp.z;
            float go = gb[b * 36 + cl + 3] + gp.w;
            float f  = sigm(gf);
            float i  = sigm(gi);
            float ch = tanhf(gc);
            float o  = sigm(go);
            float cn = f * creg[r] + i * ch;
            creg[r] = cn;
            float hr = tf32r(o * tanhf(cn));
            size_t ci = (size_t)b * 1024 + (n0 >> 2) + uu;
            hout[ci] = hr;
            hall[ci] = hr;
        }

        // ---- software grid barrier (flag/sense, monotonic) ----
        const unsigned target = base + (unsigned)t + 1u;
        __syncthreads();                            // all h writes before flag
        if (tid == 0) strel(&g_flags[bid * 32], target);
        if (bid == 0) {
            if (tid < 128) {
                while ((int)(ldacq(&g_flags[tid * 32]) - target) < 0) __nanosleep(32);
            }
            __syncthreads();
            if (tid == 0) strel(&g_sense, target);
        }
        if (tid == 0) {
            while ((int)(ldacq(&g_sense) - target) < 0) __nanosleep(32);
        }
        __syncthreads();                            // all threads see new h
    }
}

// ---------------- launch -----------------------------------------------------
extern "C" void kernel_launch(void* const* d_in, const int* in_sizes, int n_in,
                              void* d_out, int out_size) {
    const float* x    = (const float*)d_in[0];
    const float* h0   = (const float*)d_in[1];
    const float* c0   = (const float*)d_in[2];
    const float* W_f  = (const float*)d_in[3];
    const float* b_f  = (const float*)d_in[4];
    const float* W_i  = (const float*)d_in[5];
    const float* b_i  = (const float*)d_in[6];
    const float* W_c  = (const float*)d_in[7];
    const float* b_c  = (const float*)d_in[8];
    const float* W_o  = (const float*)d_in[9];
    const float* b_o  = (const float*)d_in[10];
    const float* W_out = (const float*)d_in[11];
    const float* b_out = (const float*)d_in[12];
    float* out = (float*)d_out;

    cudaFuncSetAttribute(k_gemm, cudaFuncAttributeMaxDynamicSharedMemorySize, 82944);
    cudaFuncSetAttribute(k_rec,  cudaFuncAttributeMaxDynamicSharedMemorySize, REC_SMEM);

    k_prep_x<<<32768, 256>>>(x);
    k_prep_w<<<8192, dim3(32, 8)>>>(W_f, W_i, W_c, W_o);
    k_prep_wout<<<1024, dim3(32, 8)>>>(W_out);
    k_prep_misc<<<256, 256>>>(b_f, b_i, b_c, b_o, h0, c0);

    // pre-GEMM: G_pre (M=32768, N=4096)
    k_gemm<<<dim3(64, 256), 256, 82944>>>(nullptr, nullptr, 0);

    // persistent recurrence: all 512 steps in one kernel
    k_rec<<<128, 256, REC_SMEM>>>();

    // post-GEMM: out (M=32768, N=1024)
    k_gemm<<<dim3(16, 256), 256, 82944>>>(out, b_out, 1);
}

// round 6
// speedup vs baseline: 1.1646x; 1.1301x over previous
#include <cuda_runtime.h>
#include <cstdint>
#include <math.h>

// ---------------------------------------------------------------------------
// LSTM  B=64 S=512 D=1024 H=1024 F=1024
//  1) G_pre = Xt @ WxT^T + b_g      (tf32 GEMM, M=32768 N=4096 K=1024)
//  2) ONE persistent kernel, 128 CTAs, 512 steps:
//       gates = G_pre[t] + h@WhT^T ; fused LSTM elementwise
//     W_h slice in SMEM all 512 steps; c in registers; flat all-poll barrier.
//  3) out = Hall @ WoT^T + b_out    (tf32 GEMM, M=32768 N=1024 K=1024)
// Gate columns interleaved: n = 4*unit + gate.
// Big GEMM: BM=128 BN=128 BK=32, supertiled rasterization for L2 reuse.
// ---------------------------------------------------------------------------

#define DEVINL __device__ __forceinline__

// ---------------- static device scratch (no runtime allocation) ------------
__device__ float g_Xt  [(size_t)32768 * 1024];   // x as (t,b) rows, tf32-rounded
__device__ float g_Gpre[(size_t)32768 * 4096];   // x-part of gates (+bias)
__device__ float g_Hall[(size_t)32768 * 1024];   // all h_t, tf32-rounded
__device__ float g_WxT [(size_t)4096 * 1024];    // [n][k] interleaved, x rows
__device__ float g_WhT [(size_t)4096 * 1024];    // [n][k] interleaved, h rows
__device__ float g_WoT [(size_t)1024 * 1024];    // W_out^T [f][h]
__device__ float g_bg  [4096];                   // gate bias, interleaved
__device__ float g_h   [2][64 * 1024];           // ping-pong recurrent state
__device__ float g_c   [64 * 1024];              // cell state (init only)

// grid-barrier state: monotonic counters (never reset; base read per launch)
__device__ unsigned g_flags[128 * 32];           // flag i at [i*32] (own 128B line)

// ---------------- helpers ---------------------------------------------------
DEVINL uint32_t f2tf32(float x) {
    uint32_t r; asm("cvt.rna.tf32.f32 %0, %1;" : "=r"(r) : "f"(x)); return r;
}
DEVINL float tf32r(float x) { return __uint_as_float(f2tf32(x)); }

DEVINL void cpa16(void* dst, const void* src) {
    uint32_t d = (uint32_t)__cvta_generic_to_shared(dst);
    asm volatile("cp.async.cg.shared.global [%0], [%1], 16;\n" :: "r"(d), "l"(src));
}
DEVINL void cp_commit() { asm volatile("cp.async.commit_group;\n"); }
template <int N> DEVINL void cp_wait() { asm volatile("cp.async.wait_group %0;\n" :: "n"(N)); }

DEVINL void mma_tf32(float* c, const uint32_t* a, const uint32_t* b) {
    asm volatile(
        "mma.sync.aligned.m16n8k8.row.col.f32.tf32.tf32.f32 "
        "{%0,%1,%2,%3},{%4,%5,%6,%7},{%8,%9},{%0,%1,%2,%3};\n"
        : "+f"(c[0]), "+f"(c[1]), "+f"(c[2]), "+f"(c[3])
        : "r"(a[0]), "r"(a[1]), "r"(a[2]), "r"(a[3]), "r"(b[0]), "r"(b[1]));
}
DEVINL float sigm(float x) { return 1.f / (1.f + __expf(-x)); }

DEVINL unsigned ldacq(const unsigned* p) {
    unsigned v; asm volatile("ld.acquire.gpu.global.u32 %0, [%1];" : "=r"(v) : "l"(p)); return v;
}
DEVINL void strel(unsigned* p, unsigned v) {
    asm volatile("st.release.gpu.global.u32 [%0], %1;" :: "l"(p), "r"(v));
}

// ---------------- prep kernels ---------------------------------------------
// x[b,t,d] -> g_Xt[(t*64+b)*1024 + d] (tf32-rounded). grid 32768 x 256
__global__ void __launch_bounds__(256) k_prep_x(const float* __restrict__ x) {
    size_t p = (size_t)blockIdx.x * 256 + threadIdx.x;
    int d4 = (int)(p & 255);
    size_t m = p >> 8;
    int b = (int)(m & 63), t = (int)(m >> 6);
    float4 v = *(const float4*)(x + ((size_t)b * 512 + t) * 1024 + (size_t)d4 * 4);
    v.x = tf32r(v.x); v.y = tf32r(v.y); v.z = tf32r(v.z); v.w = tf32r(v.w);
    *(float4*)(g_Xt + m * 1024 + (size_t)d4 * 4) = v;
}

// gate weights [2048,1024] -> WxT / WhT with gate interleave. grid 8192, (32,8)
__global__ void k_prep_w(const float* __restrict__ Wf, const float* __restrict__ Wi,
                         const float* __restrict__ Wc, const float* __restrict__ Wo) {
    __shared__ float tile[32][33];
    int bid = blockIdx.x;
    int s    = bid >> 12;         // 0 = x rows, 1 = h rows
    int gate = (bid >> 10) & 3;
    int kt   = (bid >> 5) & 31;
    int ut   = bid & 31;
    const float* W = (gate == 0) ? Wf : (gate == 1) ? Wi : (gate == 2) ? Wc : Wo;
    int tx = threadIdx.x, ty = threadIdx.y;
#pragma unroll
    for (int r = 0; r < 4; r++) {
        int k = kt * 32 + ty + r * 8;
        tile[ty + r * 8][tx] = W[(size_t)(s * 1024 + k) * 1024 + ut * 32 + tx];
    }
    __syncthreads();
    float* WT = s ? g_WhT : g_WxT;
#pragma unroll
    for (int r = 0; r < 4; r++) {
        int ul = ty + r * 8;
        int n = 4 * (ut * 32 + ul) + gate;
        WT[(size_t)n * 1024 + kt * 32 + tx] = tf32r(tile[tx][ul]);
    }
}

// W_out [1024][1024] -> g_WoT[f][h]. grid 1024, (32,8)
__global__ void k_prep_wout(const float* __restrict__ Wout) {
    __shared__ float tile[32][33];
    int ft = blockIdx.x & 31, ht = blockIdx.x >> 5;
    int tx = threadIdx.x, ty = threadIdx.y;
#pragma unroll
    for (int r = 0; r < 4; r++) {
        int h = ht * 32 + ty + r * 8;
        tile[ty + r * 8][tx] = Wout[(size_t)h * 1024 + ft * 32 + tx];
    }
    __syncthreads();
#pragma unroll
    for (int r = 0; r < 4; r++) {
        int fl = ty + r * 8;
        int f = ft * 32 + fl;
        g_WoT[(size_t)f * 1024 + ht * 32 + tx] = tf32r(tile[tx][fl]);
    }
}

// interleaved bias + state init. grid 256 x 256
__global__ void __launch_bounds__(256) k_prep_misc(
        const float* __restrict__ bf, const float* __restrict__ bi,
        const float* __restrict__ bc, const float* __restrict__ bo,
        const float* __restrict__ h0, const float* __restrict__ c0) {
    int i = blockIdx.x * 256 + threadIdx.x;      // 0..65535
    if (i < 4096) {
        int u = i >> 2, gt = i & 3;
        const float* b = (gt == 0) ? bf : (gt == 1) ? bi : (gt == 2) ? bc : bo;
        g_bg[i] = b[u];
    }
    g_h[0][i] = tf32r(h0[i]);
    g_c[i]    = c0[i];
}

// ---------------- big tf32 GEMM: BM=128 BN=128 BK=32, 256 thr, 3-stage -----
// warp tile 64x32 (2x4 warp grid). Supertiled rasterization (SH=8 m-blocks).
// mode 0: g_Gpre = g_Xt @ g_WxT^T + g_bg   (N=4096, 8192 CTAs)
// mode 1: out    = g_Hall @ g_WoT^T + b_out (N=1024, 2048 CTAs)
//         row m=(t*64+b) -> out[(b*512+t)*1024]
static const int GEMM_SMEM = 3 * 2 * 128 * 36 * 4;   // 110592 B

__global__ void __launch_bounds__(256, 2) k_gemm(float* __restrict__ Cpost,
                                                 const float* __restrict__ bias_post,
                                                 int mode) {
    extern __shared__ float sm[];
    const float* A  = mode ? g_Hall : g_Xt;
    const float* BT = mode ? g_WoT  : g_WxT;
    float* As = sm;                    // [3][128][36]
    float* Bs = sm + 3 * 128 * 36;     // [3][128][36]

    const int tid = threadIdx.x, lane = tid & 31, wid = tid >> 5;
    const int wm = wid & 1, wn = wid >> 1;          // 2 x 4 warps
    const int g = lane >> 2, tg = lane & 3;

    // supertiled decode: 8 m-blocks per super-row, all n-blocks inside
    int mi, ni;
    if (mode == 0) {                     // 32 n-blocks
        int sup = blockIdx.x >> 8, rem = blockIdx.x & 255;
        mi = sup * 8 + (rem & 7); ni = rem >> 3;
    } else {                             // 8 n-blocks
        int sup = blockIdx.x >> 6, rem = blockIdx.x & 63;
        mi = sup * 8 + (rem & 7); ni = rem >> 3;
    }
    const int m0 = mi * 128;
    const int n0 = ni * 128;

    float acc[4][4][4];
#pragma unroll
    for (int i = 0; i < 4; i++)
#pragma unroll
        for (int j = 0; j < 4; j++)
#pragma unroll
            for (int k = 0; k < 4; k++) acc[i][j][k] = 0.f;

    auto issue = [&](int stg, int kb) {
        float* as = As + stg * 128 * 36;
        float* bs = Bs + stg * 128 * 36;
#pragma unroll
        for (int r = 0; r < 4; r++) {
            int f = tid + r * 256; int row = f >> 3, c4 = f & 7;
            cpa16(&as[row * 36 + c4 * 4],
                  A + (size_t)(m0 + row) * 1024 + kb + c4 * 4);
        }
#pragma unroll
        for (int r = 0; r < 4; r++) {
            int f = tid + r * 256; int row = f >> 3, c4 = f & 7;
            cpa16(&bs[row * 36 + c4 * 4],
                  BT + (size_t)(n0 + row) * 1024 + kb + c4 * 4);
        }
    };

    issue(0, 0);  cp_commit();
    issue(1, 32); cp_commit();

    for (int kbi = 0; kbi < 32; kbi++) {
        cp_wait<1>();
        __syncthreads();
        const uint32_t* as = (const uint32_t*)(As + (kbi % 3) * 128 * 36);
        const uint32_t* bs = (const uint32_t*)(Bs + (kbi % 3) * 128 * 36);
#pragma unroll
        for (int kk = 0; kk < 32; kk += 8) {
            uint32_t a[4][4], b[4][2];
#pragma unroll
            for (int mt = 0; mt < 4; mt++) {
                int r0 = wm * 64 + mt * 16 + g;
                a[mt][0] = as[r0 * 36 + kk + tg];
                a[mt][1] = as[(r0 + 8) * 36 + kk + tg];
                a[mt][2] = as[r0 * 36 + kk + 4 + tg];
                a[mt][3] = as[(r0 + 8) * 36 + kk + 4 + tg];
            }
#pragma unroll
            for (int nt = 0; nt < 4; nt++) {
                int nr = wn * 32 + nt * 8 + g;
                b[nt][0] = bs[nr * 36 + kk + tg];
                b[nt][1] = bs[nr * 36 + kk + 4 + tg];
            }
#pragma unroll
            for (int mt = 0; mt < 4; mt++)
#pragma unroll
                for (int nt = 0; nt < 4; nt++) mma_tf32(acc[mt][nt], a[mt], b[nt]);
        }
        if (kbi + 2 < 32) issue((kbi + 2) % 3, (kbi + 2) * 32);
        cp_commit();
    }

    // epilogue
#pragma unroll
    for (int mt = 0; mt < 4; mt++) {
#pragma unroll
        for (int nt = 0; nt < 4; nt++) {
            int row = m0 + wm * 64 + mt * 16 + g;
            int col = n0 + wn * 32 + nt * 8 + 2 * tg;
#pragma unroll
            for (int h = 0; h < 2; h++) {
                int gr = row + h * 8;
                float b0, b1;
                float v0 = acc[mt][nt][h * 2 + 0];
                float v1 = acc[mt][nt][h * 2 + 1];
                if (mode == 0) { b0 = g_bg[col]; b1 = g_bg[col + 1]; }
                else           { b0 = bias_post[col]; b1 = bias_post[col + 1]; }
                float2 v = make_float2(v0 + b0, v1 + b1);
                if (mode == 0) {
                    *(float2*)(g_Gpre + (size_t)gr * 4096 + col) = v;
                } else {
                    size_t o = ((size_t)(gr & 63) * 512 + (gr >> 6)) * 1024 + col;
                    *(float2*)(Cpost + o) = v;
                }
            }
        }
    }
}

// ---------------- persistent recurrence: 128 CTAs x 256 thr, 512 steps -----
// CTA owns gate columns [n0, n0+32) = units [n0/4, n0/4+8). W_h slice in SMEM.
static const int WSTRIDE = 1028;                      // bank-conflict-free
static const int REC_SMEM = (32 * WSTRIDE + 3 * 64 * 36) * 4;   // 159232 B

__global__ void __launch_bounds__(256) k_rec() {
    extern __shared__ float smr[];
    float* Wsh = smr;                     // [32][1028]
    float* Ast = smr + 32 * WSTRIDE;      // 3 stages of [64][36]; aliased as gb

    const int tid = threadIdx.x, lane = tid & 31, wid = tid >> 5;
    const int wm = wid & 3, wn = wid >> 2;
    const int g = lane >> 2, tg = lane & 3;
    const int n0 = blockIdx.x * 32;
    const int bid = blockIdx.x;

    // ---- load W_h slice into SMEM (stays for all 512 steps) ----
#pragma unroll 4
    for (int j = 0; j < 32; j++) {
        int f = tid + j * 256;            // float4 index, 8192 total
        int row = f >> 8, c4 = f & 255;
        float4 v = *(const float4*)(g_WhT + (size_t)(n0 + row) * 1024 + (size_t)c4 * 4);
        *(float4*)(Wsh + row * WSTRIDE + c4 * 4) = v;
    }

    // ---- cell state in registers for the whole kernel ----
    float creg[2];
#pragma unroll
    for (int r = 0; r < 2; r++) {
        int item = tid + r * 256;
        int b = item >> 3, uu = item & 7;
        creg[r] = g_c[(size_t)b * 1024 + (n0 >> 2) + uu];
    }

    // ---- barrier base: all flags equal at launch start (monotonic) ----
    __shared__ unsigned sh_base;
    if (tid == 0) sh_base = ldacq(&g_flags[bid * 32]);
    __syncthreads();
    const unsigned base = sh_base;

    const uint32_t* wu = (const uint32_t*)Wsh;

    for (int t = 0; t < 512; t++) {
        const float* hin  = g_h[t & 1];
        float* hout       = g_h[(t + 1) & 1];
        float* hall       = g_Hall + (size_t)t * 64 * 1024;
        const float* gpre = g_Gpre + (size_t)t * 64 * 4096;

        auto issueA = [&](int stg, int kb) {
            float* as = Ast + stg * 2304;
#pragma unroll
            for (int r = 0; r < 2; r++) {
                int f = tid + r * 256; int row = f >> 3, c4 = f & 7;
                cpa16(&as[row * 36 + c4 * 4], hin + (size_t)row * 1024 + kb + c4 * 4);
            }
        };

        float acc[2][4];
#pragma unroll
        for (int i = 0; i < 2; i++)
#pragma unroll
            for (int k = 0; k < 4; k++) acc[i][k] = 0.f;

        issueA(0, 0);  cp_commit();
        issueA(1, 32); cp_commit();

        for (int kbi = 0; kbi < 32; kbi++) {
            cp_wait<1>();
            __syncthreads();
            const uint32_t* as = (const uint32_t*)(Ast + (kbi % 3) * 2304);
            const int kc = kbi * 32;
#pragma unroll
            for (int kk = 0; kk < 32; kk += 8) {
                uint32_t a[4], b[2][2];
                int r0 = wm * 16 + g;
                a[0] = as[r0 * 36 + kk + tg];
                a[1] = as[(r0 + 8) * 36 + kk + tg];
                a[2] = as[r0 * 36 + kk + 4 + tg];
                a[3] = as[(r0 + 8) * 36 + kk + 4 + tg];
#pragma unroll
                for (int nt = 0; nt < 2; nt++) {
                    int nr = wn * 16 + nt * 8 + g;
                    b[nt][0] = wu[nr * WSTRIDE + kc + kk + tg];
                    b[nt][1] = wu[nr * WSTRIDE + kc + kk + 4 + tg];
                }
                mma_tf32(acc[0], a, b[0]);
                mma_tf32(acc[1], a, b[1]);
            }
            if (kbi + 2 < 32) issueA((kbi + 2) % 3, (kbi + 2) * 32);
            cp_commit();
        }

        // ---- gate exchange through smem (alias stage memory) ----
        __syncthreads();
        float* gb = Ast;                  // [64][36], cols 0..31 used
#pragma unroll
        for (int nt = 0; nt < 2; nt++) {
            int row = wm * 16 + g, col = wn * 16 + nt * 8 + 2 * tg;
            gb[row * 36 + col]           = acc[nt][0];
            gb[row * 36 + col + 1]       = acc[nt][1];
            gb[(row + 8) * 36 + col]     = acc[nt][2];
            gb[(row + 8) * 36 + col + 1] = acc[nt][3];
        }
        __syncthreads();

        // ---- fused LSTM elementwise: 64 b x 8 units per CTA ----
#pragma unroll
        for (int r = 0; r < 2; r++) {
            int item = tid + r * 256;
            int b = item >> 3, uu = item & 7;
            int cl = 4 * uu;
            float4 gp = *(const float4*)(gpre + (size_t)b * 4096 + n0 + cl);
            float gf = gb[b * 36 + cl]     + gp.x;
            float gi = gb[b * 36 + cl + 1] + gp.y;
            float gc = gb[b * 36 + cl + 2] + gp.z;
            float go = gb[b * 36 + cl + 3] + gp.w;
            float f  = sigm(gf);
            float i  = sigm(gi);
            float ch = tanhf(gc);
            float o  = sigm(go);
            float cn = f * creg[r] + i * ch;
            creg[r] = cn;
            float hr = tf32r(o * tanhf(cn));
            size_t ci = (size_t)b * 1024 + (n0 >> 2) + uu;
            hout[ci] = hr;
            hall[ci] = hr;
        }

        // ---- flat all-poll grid barrier (monotonic flags) ----
        const unsigned target = base + (unsigned)t + 1u;
        __syncthreads();                            // all h writes done
        if (tid == 0) strel(&g_flags[bid * 32], target);
        if (tid < 128) {
            while ((int)(ldacq(&g_flags[tid * 32]) - target) < 0) __nanosleep(20);
        }
        __syncthreads();                            // all threads see new h
    }
}

// ---------------- launch -----------------------------------------------------
extern "C" void kernel_launch(void* const* d_in, const int* in_sizes, int n_in,
                              void* d_out, int out_size) {
    const float* x    = (const float*)d_in[0];
    const float* h0   = (const float*)d_in[1];
    const float* c0   = (const float*)d_in[2];
    const float* W_f  = (const float*)d_in[3];
    const float* b_f  = (const float*)d_in[4];
    const float* W_i  = (const float*)d_in[5];
    const float* b_i  = (const float*)d_in[6];
    const float* W_c  = (const float*)d_in[7];
    const float* b_c  = (const float*)d_in[8];
    const float* W_o  = (const float*)d_in[9];
    const float* b_o  = (const float*)d_in[10];
    const float* W_out = (const float*)d_in[11];
    const float* b_out = (const float*)d_in[12];
    float* out = (float*)d_out;

    cudaFuncSetAttribute(k_gemm, cudaFuncAttributeMaxDynamicSharedMemorySize, GEMM_SMEM);
    cudaFuncSetAttribute(k_rec,  cudaFuncAttributeMaxDynamicSharedMemorySize, REC_SMEM);

    k_prep_x<<<32768, 256>>>(x);
    k_prep_w<<<8192, dim3(32, 8)>>>(W_f, W_i, W_c, W_o);
    k_prep_wout<<<1024, dim3(32, 8)>>>(W_out);
    k_prep_misc<<<256, 256>>>(b_f, b_i, b_c, b_o, h0, c0);

    // pre-GEMM: G_pre (M=32768, N=4096), 8192 CTAs supertiled
    k_gemm<<<8192, 256, GEMM_SMEM>>>(nullptr, nullptr, 0);

    // persistent recurrence: all 512 steps in one kernel
    k_rec<<<128, 256, REC_SMEM>>>();

    // post-GEMM: out (M=32768, N=1024), 2048 CTAs supertiled
    k_gemm<<<2048, 256, GEMM_SMEM>>>(out, b_out, 1);
}

// round 7
// speedup vs baseline: 1.1798x; 1.0131x over previous
#include <cuda_runtime.h>
#include <cstdint>
#include <math.h>

// ---------------------------------------------------------------------------
// LSTM  B=64 S=512 D=1024 H=1024 F=1024
//  1) G_pre = Xt @ WxT^T + b_g      (tf32 GEMM, M=32768 N=4096 K=1024)
//  2) ONE persistent kernel, 128 CTAs, 512 steps:
//       gates = G_pre[t] + h@WhT^T ; fused LSTM elementwise
//     W_h slice in SMEM all 512 steps; c in registers; flat all-poll barrier.
//  3) out = Hall @ WoT^T + b_out    (tf32 GEMM, M=32768 N=1024 K=1024)
// Gate columns interleaved: n = 4*unit + gate.
// Big GEMM: BM=128 BN=128 BK=32, supertiled rasterization, NO reg cap
// (R5's __launch_bounds__(256,2) forced accumulator spills).
// ---------------------------------------------------------------------------

#define DEVINL __device__ __forceinline__

// ---------------- static device scratch (no runtime allocation) ------------
__device__ float g_Xt  [(size_t)32768 * 1024];   // x as (t,b) rows, tf32-rounded
__device__ float g_Gpre[(size_t)32768 * 4096];   // x-part of gates (+bias)
__device__ float g_Hall[(size_t)32768 * 1024];   // all h_t, tf32-rounded
__device__ float g_WxT [(size_t)4096 * 1024];    // [n][k] interleaved, x rows
__device__ float g_WhT [(size_t)4096 * 1024];    // [n][k] interleaved, h rows
__device__ float g_WoT [(size_t)1024 * 1024];    // W_out^T [f][h]
__device__ float g_bg  [4096];                   // gate bias, interleaved
__device__ float g_h   [2][64 * 1024];           // ping-pong recurrent state
__device__ float g_c   [64 * 1024];              // cell state (init only)

// grid-barrier state: monotonic counters (never reset; base read per launch)
__device__ unsigned g_flags[128 * 32];           // flag i at [i*32] (own 128B line)

// ---------------- helpers ---------------------------------------------------
DEVINL uint32_t f2tf32(float x) {
    uint32_t r; asm("cvt.rna.tf32.f32 %0, %1;" : "=r"(r) : "f"(x)); return r;
}
DEVINL float tf32r(float x) { return __uint_as_float(f2tf32(x)); }

DEVINL void cpa16(void* dst, const void* src) {
    uint32_t d = (uint32_t)__cvta_generic_to_shared(dst);
    asm volatile("cp.async.cg.shared.global [%0], [%1], 16;\n" :: "r"(d), "l"(src));
}
DEVINL void cp_commit() { asm volatile("cp.async.commit_group;\n"); }
template <int N> DEVINL void cp_wait() { asm volatile("cp.async.wait_group %0;\n" :: "n"(N)); }

DEVINL void mma_tf32(float* c, const uint32_t* a, const uint32_t* b) {
    asm volatile(
        "mma.sync.aligned.m16n8k8.row.col.f32.tf32.tf32.f32 "
        "{%0,%1,%2,%3},{%4,%5,%6,%7},{%8,%9},{%0,%1,%2,%3};\n"
        : "+f"(c[0]), "+f"(c[1]), "+f"(c[2]), "+f"(c[3])
        : "r"(a[0]), "r"(a[1]), "r"(a[2]), "r"(a[3]), "r"(b[0]), "r"(b[1]));
}
DEVINL float sigm(float x) { return 1.f / (1.f + __expf(-x)); }

DEVINL unsigned ldacq(const unsigned* p) {
    unsigned v; asm volatile("ld.acquire.gpu.global.u32 %0, [%1];" : "=r"(v) : "l"(p)); return v;
}
DEVINL void strel(unsigned* p, unsigned v) {
    asm volatile("st.release.gpu.global.u32 [%0], %1;" :: "l"(p), "r"(v));
}

// ---------------- prep kernels ---------------------------------------------
// x[b,t,d] -> g_Xt[(t*64+b)*1024 + d] (tf32-rounded). grid 32768 x 256
__global__ void __launch_bounds__(256) k_prep_x(const float* __restrict__ x) {
    size_t p = (size_t)blockIdx.x * 256 + threadIdx.x;
    int d4 = (int)(p & 255);
    size_t m = p >> 8;
    int b = (int)(m & 63), t = (int)(m >> 6);
    float4 v = *(const float4*)(x + ((size_t)b * 512 + t) * 1024 + (size_t)d4 * 4);
    v.x = tf32r(v.x); v.y = tf32r(v.y); v.z = tf32r(v.z); v.w = tf32r(v.w);
    *(float4*)(g_Xt + m * 1024 + (size_t)d4 * 4) = v;
}

// gate weights [2048,1024] -> WxT / WhT with gate interleave. grid 8192, (32,8)
__global__ void k_prep_w(const float* __restrict__ Wf, const float* __restrict__ Wi,
                         const float* __restrict__ Wc, const float* __restrict__ Wo) {
    __shared__ float tile[32][33];
    int bid = blockIdx.x;
    int s    = bid >> 12;         // 0 = x rows, 1 = h rows
    int gate = (bid >> 10) & 3;
    int kt   = (bid >> 5) & 31;
    int ut   = bid & 31;
    const float* W = (gate == 0) ? Wf : (gate == 1) ? Wi : (gate == 2) ? Wc : Wo;
    int tx = threadIdx.x, ty = threadIdx.y;
#pragma unroll
    for (int r = 0; r < 4; r++) {
        int k = kt * 32 + ty + r * 8;
        tile[ty + r * 8][tx] = W[(size_t)(s * 1024 + k) * 1024 + ut * 32 + tx];
    }
    __syncthreads();
    float* WT = s ? g_WhT : g_WxT;
#pragma unroll
    for (int r = 0; r < 4; r++) {
        int ul = ty + r * 8;
        int n = 4 * (ut * 32 + ul) + gate;
        WT[(size_t)n * 1024 + kt * 32 + tx] = tf32r(tile[tx][ul]);
    }
}

// W_out [1024][1024] -> g_WoT[f][h]. grid 1024, (32,8)
__global__ void k_prep_wout(const float* __restrict__ Wout) {
    __shared__ float tile[32][33];
    int ft = blockIdx.x & 31, ht = blockIdx.x >> 5;
    int tx = threadIdx.x, ty = threadIdx.y;
#pragma unroll
    for (int r = 0; r < 4; r++) {
        int h = ht * 32 + ty + r * 8;
        tile[ty + r * 8][tx] = Wout[(size_t)h * 1024 + ft * 32 + tx];
    }
    __syncthreads();
#pragma unroll
    for (int r = 0; r < 4; r++) {
        int fl = ty + r * 8;
        int f = ft * 32 + fl;
        g_WoT[(size_t)f * 1024 + ht * 32 + tx] = tf32r(tile[tx][fl]);
    }
}

// interleaved bias + state init. grid 256 x 256
__global__ void __launch_bounds__(256) k_prep_misc(
        const float* __restrict__ bf, const float* __restrict__ bi,
        const float* __restrict__ bc, const float* __restrict__ bo,
        const float* __restrict__ h0, const float* __restrict__ c0) {
    int i = blockIdx.x * 256 + threadIdx.x;      // 0..65535
    if (i < 4096) {
        int u = i >> 2, gt = i & 3;
        const float* b = (gt == 0) ? bf : (gt == 1) ? bi : (gt == 2) ? bc : bo;
        g_bg[i] = b[u];
    }
    g_h[0][i] = tf32r(h0[i]);
    g_c[i]    = c0[i];
}

// ---------------- big tf32 GEMM: BM=128 BN=128 BK=32, 256 thr, 3-stage -----
// warp tile 64x32 (2x4 warp grid). Supertiled rasterization (8 m-blocks).
// NO min-blocks clamp: needs ~160-200 regs/thread; 1 CTA/SM, zero spills.
// mode 0: g_Gpre = g_Xt @ g_WxT^T + g_bg   (N=4096, 8192 CTAs)
// mode 1: out    = g_Hall @ g_WoT^T + b_out (N=1024, 2048 CTAs)
//         row m=(t*64+b) -> out[(b*512+t)*1024]
static const int GEMM_SMEM = 3 * 2 * 128 * 36 * 4;   // 110592 B

__global__ void __launch_bounds__(256) k_gemm(float* __restrict__ Cpost,
                                              const float* __restrict__ bias_post,
                                              int mode) {
    extern __shared__ float sm[];
    const float* A  = mode ? g_Hall : g_Xt;
    const float* BT = mode ? g_WoT  : g_WxT;
    float* As = sm;                    // [3][128][36]
    float* Bs = sm + 3 * 128 * 36;     // [3][128][36]

    const int tid = threadIdx.x, lane = tid & 31, wid = tid >> 5;
    const int wm = wid & 1, wn = wid >> 1;          // 2 x 4 warps
    const int g = lane >> 2, tg = lane & 3;

    // supertiled decode: 8 m-blocks per super-row, all n-blocks inside
    int mi, ni;
    if (mode == 0) {                     // 32 n-blocks
        int sup = blockIdx.x >> 8, rem = blockIdx.x & 255;
        mi = sup * 8 + (rem & 7); ni = rem >> 3;
    } else {                             // 8 n-blocks
        int sup = blockIdx.x >> 6, rem = blockIdx.x & 63;
        mi = sup * 8 + (rem & 7); ni = rem >> 3;
    }
    const int m0 = mi * 128;
    const int n0 = ni * 128;

    float acc[4][4][4];
#pragma unroll
    for (int i = 0; i < 4; i++)
#pragma unroll
        for (int j = 0; j < 4; j++)
#pragma unroll
            for (int k = 0; k < 4; k++) acc[i][j][k] = 0.f;

    auto issue = [&](int stg, int kb) {
        float* as = As + stg * 128 * 36;
        float* bs = Bs + stg * 128 * 36;
#pragma unroll
        for (int r = 0; r < 4; r++) {
            int f = tid + r * 256; int row = f >> 3, c4 = f & 7;
            cpa16(&as[row * 36 + c4 * 4],
                  A + (size_t)(m0 + row) * 1024 + kb + c4 * 4);
        }
#pragma unroll
        for (int r = 0; r < 4; r++) {
            int f = tid + r * 256; int row = f >> 3, c4 = f & 7;
            cpa16(&bs[row * 36 + c4 * 4],
                  BT + (size_t)(n0 + row) * 1024 + kb + c4 * 4);
        }
    };

    issue(0, 0);  cp_commit();
    issue(1, 32); cp_commit();

    for (int kbi = 0; kbi < 32; kbi++) {
        cp_wait<1>();
        __syncthreads();
        const uint32_t* as = (const uint32_t*)(As + (kbi % 3) * 128 * 36);
        const uint32_t* bs = (const uint32_t*)(Bs + (kbi % 3) * 128 * 36);
#pragma unroll
        for (int kk = 0; kk < 32; kk += 8) {
            uint32_t a[4][4], b[4][2];
#pragma unroll
            for (int mt = 0; mt < 4; mt++) {
                int r0 = wm * 64 + mt * 16 + g;
                a[mt][0] = as[r0 * 36 + kk + tg];
                a[mt][1] = as[(r0 + 8) * 36 + kk + tg];
                a[mt][2] = as[r0 * 36 + kk + 4 + tg];
                a[mt][3] = as[(r0 + 8) * 36 + kk + 4 + tg];
            }
#pragma unroll
            for (int nt = 0; nt < 4; nt++) {
                int nr = wn * 32 + nt * 8 + g;
                b[nt][0] = bs[nr * 36 + kk + tg];
                b[nt][1] = bs[nr * 36 + kk + 4 + tg];
            }
#pragma unroll
            for (int mt = 0; mt < 4; mt++)
#pragma unroll
                for (int nt = 0; nt < 4; nt++) mma_tf32(acc[mt][nt], a[mt], b[nt]);
        }
        if (kbi + 2 < 32) issue((kbi + 2) % 3, (kbi + 2) * 32);
        cp_commit();
    }

    // epilogue
#pragma unroll
    for (int mt = 0; mt < 4; mt++) {
#pragma unroll
        for (int nt = 0; nt < 4; nt++) {
            int row = m0 + wm * 64 + mt * 16 + g;
            int col = n0 + wn * 32 + nt * 8 + 2 * tg;
#pragma unroll
            for (int h = 0; h < 2; h++) {
                int gr = row + h * 8;
                float b0, b1;
                float v0 = acc[mt][nt][h * 2 + 0];
                float v1 = acc[mt][nt][h * 2 + 1];
                if (mode == 0) { b0 = g_bg[col]; b1 = g_bg[col + 1]; }
                else           { b0 = bias_post[col]; b1 = bias_post[col + 1]; }
                float2 v = make_float2(v0 + b0, v1 + b1);
                if (mode == 0) {
                    *(float2*)(g_Gpre + (size_t)gr * 4096 + col) = v;
                } else {
                    size_t o = ((size_t)(gr & 63) * 512 + (gr >> 6)) * 1024 + col;
                    *(float2*)(Cpost + o) = v;
                }
            }
        }
    }
}

// ---------------- persistent recurrence: 128 CTAs x 256 thr, 512 steps -----
// CTA owns gate columns [n0, n0+32) = units [n0/4, n0/4+8). W_h slice in SMEM.
static const int WSTRIDE = 1028;                      // bank-conflict-free
static const int REC_SMEM = (32 * WSTRIDE + 3 * 64 * 36) * 4;   // 159232 B

__global__ void __launch_bounds__(256) k_rec() {
    extern __shared__ float smr[];
    float* Wsh = smr;                     // [32][1028]
    float* Ast = smr + 32 * WSTRIDE;      // 3 stages of [64][36]; aliased as gb

    const int tid = threadIdx.x, lane = tid & 31, wid = tid >> 5;
    const int wm = wid & 3, wn = wid >> 2;
    const int g = lane >> 2, tg = lane & 3;
    const int n0 = blockIdx.x * 32;
    const int bid = blockIdx.x;

    // ---- load W_h slice into SMEM (stays for all 512 steps) ----
#pragma unroll 4
    for (int j = 0; j < 32; j++) {
        int f = tid + j * 256;            // float4 index, 8192 total
        int row = f >> 8, c4 = f & 255;
        float4 v = *(const float4*)(g_WhT + (size_t)(n0 + row) * 1024 + (size_t)c4 * 4);
        *(float4*)(Wsh + row * WSTRIDE + c4 * 4) = v;
    }

    // ---- cell state in registers for the whole kernel ----
    float creg[2];
#pragma unroll
    for (int r = 0; r < 2; r++) {
        int item = tid + r * 256;
        int b = item >> 3, uu = item & 7;
        creg[r] = g_c[(size_t)b * 1024 + (n0 >> 2) + uu];
    }

    // ---- barrier base: all flags equal at launch start (monotonic) ----
    __shared__ unsigned sh_base;
    if (tid == 0) sh_base = ldacq(&g_flags[bid * 32]);
    __syncthreads();
    const unsigned base = sh_base;

    const uint32_t* wu = (const uint32_t*)Wsh;

    for (int t = 0; t < 512; t++) {
        const float* hin  = g_h[t & 1];
        float* hout       = g_h[(t + 1) & 1];
        float* hall       = g_Hall + (size_t)t * 64 * 1024;
        const float* gpre = g_Gpre + (size_t)t * 64 * 4096;

        auto issueA = [&](int stg, int kb) {
            float* as = Ast + stg * 2304;
#pragma unroll
            for (int r = 0; r < 2; r++) {
                int f = tid + r * 256; int row = f >> 3, c4 = f & 7;
                cpa16(&as[row * 36 + c4 * 4], hin + (size_t)row * 1024 + kb + c4 * 4);
            }
        };

        float acc[2][4];
#pragma unroll
        for (int i = 0; i < 2; i++)
#pragma unroll
            for (int k = 0; k < 4; k++) acc[i][k] = 0.f;

        issueA(0, 0);  cp_commit();
        issueA(1, 32); cp_commit();

        for (int kbi = 0; kbi < 32; kbi++) {
            cp_wait<1>();
            __syncthreads();
            const uint32_t* as = (const uint32_t*)(Ast + (kbi % 3) * 2304);
            const int kc = kbi * 32;
#pragma unroll
            for (int kk = 0; kk < 32; kk += 8) {
                uint32_t a[4], b[2][2];
                int r0 = wm * 16 + g;
                a[0] = as[r0 * 36 + kk + tg];
                a[1] = as[(r0 + 8) * 36 + kk + tg];
                a[2] = as[r0 * 36 + kk + 4 + tg];
                a[3] = as[(r0 + 8) * 36 + kk + 4 + tg];
#pragma unroll
                for (int nt = 0; nt < 2; nt++) {
                    int nr = wn * 16 + nt * 8 + g;
                    b[nt][0] = wu[nr * WSTRIDE + kc + kk + tg];
                    b[nt][1] = wu[nr * WSTRIDE + kc + kk + 4 + tg];
                }
                mma_tf32(acc[0], a, b[0]);
                mma_tf32(acc[1], a, b[1]);
            }
            if (kbi + 2 < 32) issueA((kbi + 2) % 3, (kbi + 2) * 32);
            cp_commit();
        }

        // ---- gate exchange through smem (alias stage memory) ----
        __syncthreads();
        float* gb = Ast;                  // [64][36], cols 0..31 used
#pragma unroll
        for (int nt = 0; nt < 2; nt++) {
            int row = wm * 16 + g, col = wn * 16 + nt * 8 + 2 * tg;
            gb[row * 36 + col]           = acc[nt][0];
            gb[row * 36 + col + 1]       = acc[nt][1];
            gb[(row + 8) * 36 + col]     = acc[nt][2];
            gb[(row + 8) * 36 + col + 1] = acc[nt][3];
        }
        __syncthreads();

        // ---- fused LSTM elementwise: 64 b x 8 units per CTA ----
#pragma unroll
        for (int r = 0; r < 2; r++) {
            int item = tid + r * 256;
            int b = item >> 3, uu = item & 7;
            int cl = 4 * uu;
            float4 gp = *(const float4*)(gpre + (size_t)b * 4096 + n0 + cl);
            float gf = gb[b * 36 + cl]     + gp.x;
            float gi = gb[b * 36 + cl + 1] + gp.y;
            float gc = gb[b * 36 + cl + 2] + gp.z;
            float go = gb[b * 36 + cl + 3] + gp.w;
            float f  = sigm(gf);
            float i  = sigm(gi);
            float ch = tanhf(gc);
            float o  = sigm(go);
            float cn = f * creg[r] + i * ch;
            creg[r] = cn;
            float hr = tf32r(o * tanhf(cn));
            size_t ci = (size_t)b * 1024 + (n0 >> 2) + uu;
            hout[ci] = hr;
            hall[ci] = hr;
        }

        // ---- flat all-poll grid barrier (monotonic flags) ----
        const unsigned target = base + (unsigned)t + 1u;
        __syncthreads();                            // all h writes done
        if (tid == 0) strel(&g_flags[bid * 32], target);
        if (tid < 128) {
            while ((int)(ldacq(&g_flags[tid * 32]) - target) < 0) __nanosleep(20);
        }
        __syncthreads();                            // all threads see new h
    }
}

// ---------------- launch -----------------------------------------------------
extern "C" void kernel_launch(void* const* d_in, const int* in_sizes, int n_in,
                              void* d_out, int out_size) {
    const float* x    = (const float*)d_in[0];
    const float* h0   = (const float*)d_in[1];
    const float* c0   = (const float*)d_in[2];
    const float* W_f  = (const float*)d_in[3];
    const float* b_f  = (const float*)d_in[4];
    const float* W_i  = (const float*)d_in[5];
    const float* b_i  = (const float*)d_in[6];
    const float* W_c  = (const float*)d_in[7];
    const float* b_c  = (const float*)d_in[8];
    const float* W_o  = (const float*)d_in[9];
    const float* b_o  = (const float*)d_in[10];
    const float* W_out = (const float*)d_in[11];
    const float* b_out = (const float*)d_in[12];
    float* out = (float*)d_out;

    cudaFuncSetAttribute(k_gemm, cudaFuncAttributeMaxDynamicSharedMemorySize, GEMM_SMEM);
    cudaFuncSetAttribute(k_rec,  cudaFuncAttributeMaxDynamicSharedMemorySize, REC_SMEM);

    // Order chosen so launch slot 4 (ncu -s 5 -c 1 with 2 harness launches
    // ahead) is the pre-GEMM: prep_x, prep_w, prep_misc, GEMM, ...
    k_prep_x<<<32768, 256>>>(x);
    k_prep_w<<<8192, dim3(32, 8)>>>(W_f, W_i, W_c, W_o);
    k_prep_misc<<<256, 256>>>(b_f, b_i, b_c, b_o, h0, c0);

    // pre-GEMM: G_pre (M=32768, N=4096), 8192 CTAs supertiled
    k_gemm<<<8192, 256, GEMM_SMEM>>>(nullptr, nullptr, 0);

    k_prep_wout<<<1024, dim3(32, 8)>>>(W_out);

    // persistent recurrence: all 512 steps in one kernel
    k_rec<<<128, 256, REC_SMEM>>>();

    // post-GEMM: out (M=32768, N=1024), 2048 CTAs supertiled
    k_gemm<<<2048, 256, GEMM_SMEM>>>(out, b_out, 1);
}